// round 6
// baseline (speedup 1.0000x reference)
#include <cuda_runtime.h>
#include <cuda_bf16.h>

#define NN 50000
#define EE 800000
#define IN_DIM 256
#define HID 128
#define OUT_DIM 64
#define NOFF (NN * OUT_DIM)

// ------------------------- device scratch (static, allowed) -------------------------
__device__ int   g_count[NN];
__device__ int   g_cursor[NN];
__device__ int   g_offsets[NN + 1];
__device__ int   g_srclist[EE];
__device__ int   g_src[EE];
__device__ int   g_dst[EE];
__device__ float g_dis[NN];
__device__ float g_hw1[NN * HID];   // dis[row] * (x @ W1^T)
__device__ float g_hs[NN * HID];    // dis[row] * relu(agg1 + b1)
__device__ float g_g[NN * HID];     // Agg(h)
__device__ int   g_is64;

typedef unsigned long long ull;

// ------------------------- f32x2 helpers -------------------------
__device__ __forceinline__ ull fma2(ull a, ull b, ull c) {
    ull d;
    asm("fma.rn.f32x2 %0, %1, %2, %3;" : "=l"(d) : "l"(a), "l"(b), "l"(c));
    return d;
}
__device__ __forceinline__ float2 upk2(ull a) {
    float2 f;
    asm("mov.b64 {%0, %1}, %2;" : "=f"(f.x), "=f"(f.y) : "l"(a));
    return f;
}
// horizontal sum of packed pair
__device__ __forceinline__ float hsum2(ull a) {
    float2 f = upk2(a);
    return f.x + f.y;
}

// ------------------------- small setup kernels --------------------------------------
__global__ void detect_kernel(const void* ei) {
    int lane = threadIdx.x;
    const long long* p = (const long long*)ei;
    int ok = 1;
    for (int i = lane; i < 1024; i += 32) {
        long long v = p[i];
        if (v < 0 || v >= NN) ok = 0;
    }
    unsigned m = __ballot_sync(0xffffffffu, ok);
    if (lane == 0) g_is64 = (m == 0xffffffffu) ? 1 : 0;
}

__global__ void convert_hist_kernel(const void* ei) {
    int i = blockIdx.x * blockDim.x + threadIdx.x;
    if (i >= EE) return;
    int s, d;
    if (g_is64) {
        const long long* p = (const long long*)ei;
        s = (int)p[i];
        d = (int)p[EE + i];
    } else {
        const int* p = (const int*)ei;
        s = p[i];
        d = p[EE + i];
    }
    s = min(max(s, 0), NN - 1);
    d = min(max(d, 0), NN - 1);
    g_src[i] = s;
    g_dst[i] = d;
    atomicAdd(&g_count[d], 1);
}

__global__ void dis_kernel() {
    int i = blockIdx.x * blockDim.x + threadIdx.x;
    if (i < NN) g_dis[i] = rsqrtf((float)(g_count[i] + 1));   // +1 self-loop
}

// single-block exclusive scan of g_count -> g_offsets
__global__ __launch_bounds__(1024) void scan_kernel() {
    const int T = 1024, PER = (NN + T - 1) / T;   // 49
    int tid = threadIdx.x;
    int base = tid * PER;
    int run = 0;
    for (int i = 0; i < PER; i++) {
        int idx = base + i;
        if (idx < NN) run += g_count[idx];
    }
    __shared__ int wsum[32];
    int lane = tid & 31, wid = tid >> 5;
    int inc = run;
    for (int d = 1; d < 32; d <<= 1) {
        int t = __shfl_up_sync(0xffffffffu, inc, d);
        if (lane >= d) inc += t;
    }
    if (lane == 31) wsum[wid] = inc;
    __syncthreads();
    if (wid == 0) {
        int w = wsum[lane];
        for (int d = 1; d < 32; d <<= 1) {
            int t = __shfl_up_sync(0xffffffffu, w, d);
            if (lane >= d) w += t;
        }
        wsum[lane] = w;
    }
    __syncthreads();
    int warpbase = (wid == 0) ? 0 : wsum[wid - 1];
    int acc = warpbase + inc - run;
    for (int i = 0; i < PER; i++) {
        int idx = base + i;
        if (idx <= NN) {
            g_offsets[idx] = acc;
            if (idx < NN) acc += g_count[idx];
        }
    }
}

__global__ void scatter_kernel() {
    int i = blockIdx.x * blockDim.x + threadIdx.x;
    if (i >= EE) return;
    int d = g_dst[i];
    int pos = g_offsets[d] + atomicAdd(&g_cursor[d], 1);
    g_srclist[pos] = g_src[i];
}

// ------------------------- k-paired W smem layout helper -----------------------------
// F(k,c) = (k>>1)*2C + (c>>1)*4 + ((c&1)<<1) + (k&1)
// Read: lane reads ulonglong2 at [kp*(C/2... scaled)] giving cols (2q, 2q+1), k's (2kp, 2kp+1).

// ------------------------- GEMM1: g_hw1 = dis[row] * (x @ W1^T) ----------------------
// Block 512 = 16 warps; warp = 8 rows x 64 cols; k-packed fma2, no repack movs.
// Wsm: 128 kp x 256 floats (k-paired layout) = 128KB. xsm: [64][256] = 64KB.
__global__ __launch_bounds__(512, 1)
void gemm1_kernel(const float* __restrict__ x, const float* __restrict__ W1) {
    extern __shared__ float sm[];
    float* Wsm = sm;                 // 32768 floats
    float* xsm = sm + 32768;         // [64][256]
    int tid = threadIdx.x, lane = tid & 31, warp = tid >> 5;
    int rg = warp >> 1, cg = warp & 1;

    // stage W once per block. o scattered across lanes (STS 2-way conflict max),
    // kq in mid bits (LDG pulls 32 separate 16B lines; 128KB one-time cost).
#pragma unroll
    for (int it = 0; it < 16; it++) {
        int idx = tid + it * 512;                       // 0..8191
        int o  = (idx & 31) | (((idx >> 11) & 3) << 5); // 0..127
        int kq = (idx >> 5) & 63;                       // 0..63
        float4 w = ((const float4*)W1)[o * 64 + kq];
        float wv0 = w.x, wv1 = w.y, wv2 = w.z, wv3 = w.w;
        int ob = (o >> 1) * 4 + ((o & 1) << 1);
        int k0 = kq * 4;
        Wsm[((k0 + 0) >> 1) * 256 + ob + ((k0 + 0) & 1)] = wv0;
        Wsm[((k0 + 1) >> 1) * 256 + ob + ((k0 + 1) & 1)] = wv1;
        Wsm[((k0 + 2) >> 1) * 256 + ob + ((k0 + 2) & 1)] = wv2;
        Wsm[((k0 + 3) >> 1) * 256 + ob + ((k0 + 3) & 1)] = wv3;
    }

    const int RB = 64;
    int nblk = (NN + RB - 1) / RB;
    const ulonglong2* wp = (const ulonglong2*)Wsm + cg * 32 + lane;  // stride 64 u128 per kp

    for (int blk = blockIdx.x; blk < nblk; blk += gridDim.x) {
        int row0 = blk * RB;
        __syncthreads();
#pragma unroll
        for (int i = 0; i < 8; i++) {            // 4096 float4 = 64x256
            int lin = tid + 512 * i;
            int r = lin >> 6, c4 = lin & 63;
            int row = row0 + r;
            float4 v = make_float4(0.f, 0.f, 0.f, 0.f);
            if (row < NN) v = ((const float4*)x)[row * 64 + c4];
            ((float4*)xsm)[r * 64 + c4] = v;
        }
        __syncthreads();

        ull acc[8][2];
#pragma unroll
        for (int r = 0; r < 8; r++) { acc[r][0] = 0ULL; acc[r][1] = 0ULL; }
        const float* xr = xsm + (rg * 8) * IN_DIM;

#pragma unroll 2
        for (int kp = 0; kp < 128; kp += 2) {    // 4 k per iteration
            ulonglong2 wa = wp[kp * 64];         // cols (c0,c1), k (2kp, 2kp+1)
            ulonglong2 wb = wp[(kp + 1) * 64];   // cols (c0,c1), k (2kp+2, 2kp+3)
#pragma unroll
            for (int r = 0; r < 8; r++) {
                ulonglong2 xv = *(const ulonglong2*)(xr + r * IN_DIM + kp * 2);
                acc[r][0] = fma2(xv.x, wa.x, acc[r][0]);
                acc[r][1] = fma2(xv.x, wa.y, acc[r][1]);
                acc[r][0] = fma2(xv.y, wb.x, acc[r][0]);
                acc[r][1] = fma2(xv.y, wb.y, acc[r][1]);
            }
        }

        int c0 = 2 * (cg * 32 + lane);           // even col, pair (c0, c0+1)
#pragma unroll
        for (int r = 0; r < 8; r++) {
            int row = row0 + rg * 8 + r;
            if (row < NN) {
                float di = g_dis[row];
                float2 v;
                v.x = di * hsum2(acc[r][0]);
                v.y = di * hsum2(acc[r][1]);
                *(float2*)(g_hw1 + row * HID + c0) = v;
            }
        }
    }
}

// ------------------------- aggregation: warp per destination node -------------------
template <bool RELU>
__device__ __forceinline__ void agg_body(const float* __restrict__ feat,
                                         float* __restrict__ out,
                                         const float* __restrict__ bias) {
    int gw = (blockIdx.x * blockDim.x + threadIdx.x) >> 5;
    int lane = threadIdx.x & 31;
    if (gw >= NN) return;
    int beg = g_offsets[gw], end = g_offsets[gw + 1];
    const float4* f4 = (const float4*)feat;
    float4 acc = f4[gw * 32 + lane];      // self-loop term
    int p = beg;
    for (; p + 1 < end; p += 2) {
        int s0 = g_srclist[p], s1 = g_srclist[p + 1];
        float4 v0 = f4[s0 * 32 + lane];
        float4 v1 = f4[s1 * 32 + lane];
        acc.x += v0.x; acc.y += v0.y; acc.z += v0.z; acc.w += v0.w;
        acc.x += v1.x; acc.y += v1.y; acc.z += v1.z; acc.w += v1.w;
    }
    if (p < end) {
        int s = g_srclist[p];
        float4 v = f4[s * 32 + lane];
        acc.x += v.x; acc.y += v.y; acc.z += v.z; acc.w += v.w;
    }
    float di = g_dis[gw];
    float4 r;
    if (RELU) {
        float4 b = ((const float4*)bias)[lane];
        r.x = di * fmaxf(fmaf(di, acc.x, b.x), 0.f);
        r.y = di * fmaxf(fmaf(di, acc.y, b.y), 0.f);
        r.z = di * fmaxf(fmaf(di, acc.z, b.z), 0.f);
        r.w = di * fmaxf(fmaf(di, acc.w, b.w), 0.f);
    } else {
        r.x = di * acc.x; r.y = di * acc.y; r.z = di * acc.z; r.w = di * acc.w;
    }
    ((float4*)out)[gw * 32 + lane] = r;
}

__global__ __launch_bounds__(256) void agg1_kernel(const float* __restrict__ b1) {
    agg_body<true>(g_hw1, g_hs, b1);
}
__global__ __launch_bounds__(256) void agg2_kernel() {
    agg_body<false>(g_hs, g_g, nullptr);
}

// ------------------------- GEMM2: [mu | lv] = g_g @ [Wmu;Wlv]^T + [bmu;blv] ----------
// Same k-packed design. Wsm: 64 kp x 256 floats = 64KB; xsm [64][128] = 32KB -> 2 blocks/SM.
__global__ __launch_bounds__(512, 2)
void gemm2_kernel(const float* __restrict__ Wmu, const float* __restrict__ bmu,
                  const float* __restrict__ Wlv, const float* __restrict__ blv,
                  float* __restrict__ out) {
    extern __shared__ float sm[];
    float* Wsm = sm;                 // 16384 floats
    float* xsm = sm + 16384;         // [64][128]
    int tid = threadIdx.x, lane = tid & 31, warp = tid >> 5;
    int rg = warp >> 1, cg = warp & 1;

#pragma unroll
    for (int it = 0; it < 8; it++) {
        int idx = tid + it * 512;                        // 0..4095
        int o  = (idx & 31) | (((idx >> 10) & 3) << 5);  // 0..127
        int kq = (idx >> 5) & 31;                        // 0..31
        float4 w = (o < OUT_DIM) ? ((const float4*)Wmu)[o * 32 + kq]
                                 : ((const float4*)Wlv)[(o - OUT_DIM) * 32 + kq];
        float wv0 = w.x, wv1 = w.y, wv2 = w.z, wv3 = w.w;
        int ob = (o >> 1) * 4 + ((o & 1) << 1);
        int k0 = kq * 4;
        Wsm[((k0 + 0) >> 1) * 256 + ob + ((k0 + 0) & 1)] = wv0;
        Wsm[((k0 + 1) >> 1) * 256 + ob + ((k0 + 1) & 1)] = wv1;
        Wsm[((k0 + 2) >> 1) * 256 + ob + ((k0 + 2) & 1)] = wv2;
        Wsm[((k0 + 3) >> 1) * 256 + ob + ((k0 + 3) & 1)] = wv3;
    }

    const int RB = 64;
    int nblk = (NN + RB - 1) / RB;
    const ulonglong2* wpt = (const ulonglong2*)Wsm + cg * 32 + lane;

    int c0 = 2 * (cg * 32 + lane);           // 0..126 even; <64 -> mu, else lv
    float2 bv;
    float* obase;
    if (c0 < OUT_DIM) { bv = *(const float2*)(bmu + c0); obase = out; }
    else              { bv = *(const float2*)(blv + c0 - OUT_DIM); obase = out + NOFF - OUT_DIM; }

    for (int blk = blockIdx.x; blk < nblk; blk += gridDim.x) {
        int row0 = blk * RB;
        __syncthreads();
#pragma unroll
        for (int i = 0; i < 4; i++) {            // 2048 float4 = 64x128
            int lin = tid + 512 * i;
            int r = lin >> 5, c4 = lin & 31;
            int row = row0 + r;
            float4 v = make_float4(0.f, 0.f, 0.f, 0.f);
            if (row < NN) v = ((const float4*)g_g)[row * 32 + c4];
            ((float4*)xsm)[r * 32 + c4] = v;
        }
        __syncthreads();

        ull acc[8][2];
#pragma unroll
        for (int r = 0; r < 8; r++) { acc[r][0] = 0ULL; acc[r][1] = 0ULL; }
        const float* xr = xsm + (rg * 8) * HID;

#pragma unroll 2
        for (int kp = 0; kp < 64; kp += 2) {
            ulonglong2 wa = wpt[kp * 64];
            ulonglong2 wb = wpt[(kp + 1) * 64];
#pragma unroll
            for (int r = 0; r < 8; r++) {
                ulonglong2 xv = *(const ulonglong2*)(xr + r * HID + kp * 2);
                acc[r][0] = fma2(xv.x, wa.x, acc[r][0]);
                acc[r][1] = fma2(xv.x, wa.y, acc[r][1]);
                acc[r][0] = fma2(xv.y, wb.x, acc[r][0]);
                acc[r][1] = fma2(xv.y, wb.y, acc[r][1]);
            }
        }

#pragma unroll
        for (int r = 0; r < 8; r++) {
            int row = row0 + rg * 8 + r;
            if (row < NN) {
                float2 v;
                v.x = hsum2(acc[r][0]) + bv.x;
                v.y = hsum2(acc[r][1]) + bv.y;
                *(float2*)(obase + row * OUT_DIM + c0) = v;
            }
        }
    }
}

// ------------------------- launch --------------------------------------------------
// ncu (-s 5 -c 1) profiles the 4th kernel launch in this stream; gemm1 sits there.
extern "C" void kernel_launch(void* const* d_in, const int* in_sizes, int n_in,
                              void* d_out, int out_size) {
    const float* x   = (const float*)d_in[0];
    const void*  ei  = d_in[1];
    const float* W1  = (const float*)d_in[2];
    const float* b1  = (const float*)d_in[3];
    const float* Wmu = (const float*)d_in[4];
    const float* bmu = (const float*)d_in[5];
    const float* Wlv = (const float*)d_in[6];
    const float* blv = (const float*)d_in[7];
    float* out = (float*)d_out;

    void* p_count;  cudaGetSymbolAddress(&p_count, g_count);
    void* p_cursor; cudaGetSymbolAddress(&p_cursor, g_cursor);

    const int SMEM1 = (32768 + 64 * IN_DIM) * (int)sizeof(float);   // 128KB + 64KB = 196,608 B
    const int SMEM2 = (16384 + 64 * HID) * (int)sizeof(float);      //  64KB + 32KB =  98,304 B
    cudaFuncSetAttribute(gemm1_kernel, cudaFuncAttributeMaxDynamicSharedMemorySize, SMEM1);
    cudaFuncSetAttribute(gemm2_kernel, cudaFuncAttributeMaxDynamicSharedMemorySize, SMEM2);

    cudaMemsetAsync(p_count, 0, NN * sizeof(int));
    cudaMemsetAsync(p_cursor, 0, NN * sizeof(int));

    detect_kernel<<<1, 32>>>(ei);                                // kernel #1
    convert_hist_kernel<<<(EE + 255) / 256, 256>>>(ei);          // kernel #2
    dis_kernel<<<(NN + 255) / 256, 256>>>();                     // kernel #3

    gemm1_kernel<<<148, 512, SMEM1>>>(x, W1);                    // kernel #4  <- profiled

    scan_kernel<<<1, 1024>>>();                                  // kernel #5
    scatter_kernel<<<(EE + 255) / 256, 256>>>();                 // kernel #6

    int agg_blocks = (NN * 32 + 255) / 256;   // one warp per node
    agg1_kernel<<<agg_blocks, 256>>>(b1);                        // kernel #7
    agg2_kernel<<<agg_blocks, 256>>>();                          // kernel #8

    gemm2_kernel<<<296, 512, SMEM2>>>(Wmu, bmu, Wlv, blv, out);  // kernel #9
}

// round 8
// speedup vs baseline: 1.2251x; 1.2251x over previous
#include <cuda_runtime.h>
#include <cuda_bf16.h>
#include <cstdint>

#define NN 50000
#define EE 800000
#define IN_DIM 256
#define HID 128
#define OUT_DIM 64
#define WS 129
#define NOFF (NN * OUT_DIM)

// ------------------------- device scratch -------------------------
__device__ int   g_count[NN];
__device__ int   g_cursor[NN];
__device__ int   g_offsets[NN + 1];
__device__ int   g_srclist[EE];
__device__ int   g_src[EE];
__device__ int   g_dst[EE];
__device__ float g_dis[NN];
__device__ float g_hw1[NN * HID];
__device__ float g_hs[NN * HID];
__device__ float g_g[NN * HID];
__device__ int   g_is64;

typedef unsigned long long ull;

// ------------------------- f32x2 helpers (fp32 gemm2) -------------------------
__device__ __forceinline__ ull pk2(float a, float b) {
    ull r; asm("mov.b64 %0, {%1, %2};" : "=l"(r) : "f"(a), "f"(b)); return r;
}
__device__ __forceinline__ ull fma2(ull a, ull b, ull c) {
    ull d; asm("fma.rn.f32x2 %0, %1, %2, %3;" : "=l"(d) : "l"(a), "l"(b), "l"(c)); return d;
}
__device__ __forceinline__ float2 upk2(ull a) {
    float2 f; asm("mov.b64 {%0, %1}, %2;" : "=f"(f.x), "=f"(f.y) : "l"(a)); return f;
}

// ------------------------- mma helpers -------------------------
__device__ __forceinline__ uint32_t smem_u32(const void* p) {
    uint32_t a;
    asm("{ .reg .u64 t; cvta.to.shared.u64 t, %1; cvt.u32.u64 %0, t; }" : "=r"(a) : "l"(p));
    return a;
}
__device__ __forceinline__ void ldsm_x4(uint32_t addr, uint32_t& r0, uint32_t& r1,
                                        uint32_t& r2, uint32_t& r3) {
    asm volatile("ldmatrix.sync.aligned.m8n8.x4.shared.b16 {%0,%1,%2,%3}, [%4];"
                 : "=r"(r0), "=r"(r1), "=r"(r2), "=r"(r3) : "r"(addr));
}
__device__ __forceinline__ void mma_bf16(float* d, uint32_t a0, uint32_t a1, uint32_t a2,
                                         uint32_t a3, uint32_t b0, uint32_t b1) {
    asm volatile(
        "mma.sync.aligned.m16n8k16.row.col.f32.bf16.bf16.f32 "
        "{%0,%1,%2,%3}, {%4,%5,%6,%7}, {%8,%9}, {%0,%1,%2,%3};"
        : "+f"(d[0]), "+f"(d[1]), "+f"(d[2]), "+f"(d[3])
        : "r"(a0), "r"(a1), "r"(a2), "r"(a3), "r"(b0), "r"(b1));
}
__device__ __forceinline__ uint32_t pack_bf16(float a, float b) {
    __nv_bfloat162 p = __floats2bfloat162_rn(a, b);
    return *reinterpret_cast<uint32_t*>(&p);
}
__device__ __forceinline__ float bf16_hi(float v) {
    return __bfloat162float(__float2bfloat16(v));
}

// ------------------------- small setup kernels -------------------------
__global__ void detect_kernel(const void* ei) {
    int lane = threadIdx.x;
    const long long* p = (const long long*)ei;
    int ok = 1;
    for (int i = lane; i < 1024; i += 32) {
        long long v = p[i];
        if (v < 0 || v >= NN) ok = 0;
    }
    unsigned m = __ballot_sync(0xffffffffu, ok);
    if (lane == 0) g_is64 = (m == 0xffffffffu) ? 1 : 0;
}

__global__ void convert_hist_kernel(const void* ei) {
    int i = blockIdx.x * blockDim.x + threadIdx.x;
    if (i >= EE) return;
    int s, d;
    if (g_is64) {
        const long long* p = (const long long*)ei;
        s = (int)p[i]; d = (int)p[EE + i];
    } else {
        const int* p = (const int*)ei;
        s = p[i]; d = p[EE + i];
    }
    s = min(max(s, 0), NN - 1);
    d = min(max(d, 0), NN - 1);
    g_src[i] = s; g_dst[i] = d;
    atomicAdd(&g_count[d], 1);
}

__global__ void dis_kernel() {
    int i = blockIdx.x * blockDim.x + threadIdx.x;
    if (i < NN) g_dis[i] = rsqrtf((float)(g_count[i] + 1));
}

__global__ __launch_bounds__(1024) void scan_kernel() {
    const int T = 1024, PER = (NN + T - 1) / T;
    int tid = threadIdx.x;
    int base = tid * PER;
    int run = 0;
    for (int i = 0; i < PER; i++) { int idx = base + i; if (idx < NN) run += g_count[idx]; }
    __shared__ int wsum[32];
    int lane = tid & 31, wid = tid >> 5;
    int inc = run;
    for (int d = 1; d < 32; d <<= 1) {
        int t = __shfl_up_sync(0xffffffffu, inc, d);
        if (lane >= d) inc += t;
    }
    if (lane == 31) wsum[wid] = inc;
    __syncthreads();
    if (wid == 0) {
        int w = wsum[lane];
        for (int d = 1; d < 32; d <<= 1) {
            int t = __shfl_up_sync(0xffffffffu, w, d);
            if (lane >= d) w += t;
        }
        wsum[lane] = w;
    }
    __syncthreads();
    int warpbase = (wid == 0) ? 0 : wsum[wid - 1];
    int acc = warpbase + inc - run;
    for (int i = 0; i < PER; i++) {
        int idx = base + i;
        if (idx <= NN) {
            g_offsets[idx] = acc;
            if (idx < NN) acc += g_count[idx];
        }
    }
}

__global__ void scatter_kernel() {
    int i = blockIdx.x * blockDim.x + threadIdx.x;
    if (i >= EE) return;
    int d = g_dst[i];
    int pos = g_offsets[d] + atomicAdd(&g_cursor[d], 1);
    g_srclist[pos] = g_src[i];
}

// ------------------------- GEMM1 via mma.sync bf16 hi/lo -----------------------------
// D = Ahi.Bhi^T + Alo.Bhi^T + Ahi.Blo^T, fp32 accum.
// smem bf16 tiles, row stride 264 (528B, odd multiple of 16B -> LDSM conflict-free):
//   whi @0 (128x264), wlo @67584, xhi @135168 (64x264), xlo @168960. Total 202752B.
#define SROW 528          // bytes per smem row
#define OFF_WHI 0
#define OFF_WLO 67584
#define OFF_XHI 135168
#define OFF_XLO 168960
#define G1_SMEM 202752

__global__ __launch_bounds__(256, 1)
void gemm1_mma_kernel(const float* __restrict__ x, const float* __restrict__ W1) {
    extern __shared__ char smc[];
    uint32_t su = smem_u32(smc);
    int tid = threadIdx.x, lane = tid & 31, warp = tid >> 5;
    int wr = warp & 3;          // row group: 16 rows each
    int wc = warp >> 2;         // col half: 64 cols each

    // ---- stage W hi/lo once per block: 128 rows x 64 float4 ----
#pragma unroll
    for (int it = 0; it < 32; it++) {
        int idx = it * 256 + tid;
        int o = idx >> 6, kq = idx & 63;
        float4 v = ((const float4*)W1)[o * 64 + kq];
        float hx = bf16_hi(v.x), hy = bf16_hi(v.y), hz = bf16_hi(v.z), hw = bf16_hi(v.w);
        uint2 hp = make_uint2(pack_bf16(hx, hy), pack_bf16(hz, hw));
        uint2 lp = make_uint2(pack_bf16(v.x - hx, v.y - hy), pack_bf16(v.z - hz, v.w - hw));
        *reinterpret_cast<uint2*>(smc + OFF_WHI + o * SROW + kq * 8) = hp;
        *reinterpret_cast<uint2*>(smc + OFF_WLO + o * SROW + kq * 8) = lp;
    }

    // per-lane ldmatrix source addresses (offsets within tile)
    uint32_t a_off = (uint32_t)((wr * 16 + (lane & 15)) * SROW + ((lane >> 4) << 3) * 2);
    uint32_t b_row = (uint32_t)((lane & 7) + ((lane >> 4) << 3));
    uint32_t b_off = (uint32_t)((wc * 64 + b_row) * SROW + (((lane >> 3) & 1) << 3) * 2);

    const int NT = (NN + 63) / 64;   // 782 tiles
    for (int t = blockIdx.x; t < NT; t += gridDim.x) {
        int row0 = t * 64;
        __syncthreads();
        // ---- stage x hi/lo: 64 rows x 64 float4 ----
#pragma unroll
        for (int it = 0; it < 16; it++) {
            int idx = it * 256 + tid;
            int r = idx >> 6, kq = idx & 63;
            int grow = row0 + r;
            float4 v = make_float4(0.f, 0.f, 0.f, 0.f);
            if (grow < NN) v = ((const float4*)x)[grow * 64 + kq];
            float hx = bf16_hi(v.x), hy = bf16_hi(v.y), hz = bf16_hi(v.z), hw = bf16_hi(v.w);
            uint2 hp = make_uint2(pack_bf16(hx, hy), pack_bf16(hz, hw));
            uint2 lp = make_uint2(pack_bf16(v.x - hx, v.y - hy), pack_bf16(v.z - hz, v.w - hw));
            *reinterpret_cast<uint2*>(smc + OFF_XHI + r * SROW + kq * 8) = hp;
            *reinterpret_cast<uint2*>(smc + OFF_XLO + r * SROW + kq * 8) = lp;
        }
        __syncthreads();

        float acc[8][4];
#pragma unroll
        for (int j = 0; j < 8; j++)
#pragma unroll
            for (int q = 0; q < 4; q++) acc[j][q] = 0.f;

#pragma unroll 1
        for (int pass = 0; pass < 3; pass++) {
            uint32_t ab = su + ((pass == 1) ? OFF_XLO : OFF_XHI) + a_off;
            uint32_t bb = su + ((pass == 2) ? OFF_WLO : OFF_WHI) + b_off;
#pragma unroll
            for (int ks = 0; ks < 16; ks++) {
                uint32_t a0, a1, a2, a3;
                ldsm_x4(ab + ks * 32, a0, a1, a2, a3);
#pragma unroll
                for (int j = 0; j < 4; j++) {
                    uint32_t b0, b1, b2, b3;
                    ldsm_x4(bb + j * 16 * SROW + ks * 32, b0, b1, b2, b3);
                    mma_bf16(acc[2 * j],     a0, a1, a2, a3, b0, b1);
                    mma_bf16(acc[2 * j + 1], a0, a1, a2, a3, b2, b3);
                }
            }
        }

        // ---- epilogue: c0=D[g][2t], c1=D[g][2t+1], c2=D[g+8][2t], c3=D[g+8][2t+1] ----
        int g = lane >> 2, tt = lane & 3;
        int r0g = row0 + wr * 16 + g;
        int r1g = r0g + 8;
        float di0 = (r0g < NN) ? g_dis[r0g] : 0.f;
        float di1 = (r1g < NN) ? g_dis[r1g] : 0.f;
#pragma unroll
        for (int j = 0; j < 8; j++) {
            int c = wc * 64 + j * 8 + 2 * tt;
            if (r0g < NN)
                *reinterpret_cast<float2*>(g_hw1 + r0g * HID + c) =
                    make_float2(di0 * acc[j][0], di0 * acc[j][1]);
            if (r1g < NN)
                *reinterpret_cast<float2*>(g_hw1 + r1g * HID + c) =
                    make_float2(di1 * acc[j][2], di1 * acc[j][3]);
        }
    }
}

// ------------------------- aggregation: warp per destination node -------------------
template <bool RELU>
__device__ __forceinline__ void agg_body(const float* __restrict__ feat,
                                         float* __restrict__ out,
                                         const float* __restrict__ bias) {
    int gw = (blockIdx.x * blockDim.x + threadIdx.x) >> 5;
    int lane = threadIdx.x & 31;
    if (gw >= NN) return;
    int beg = g_offsets[gw], end = g_offsets[gw + 1];
    const float4* f4 = (const float4*)feat;
    float4 acc = f4[gw * 32 + lane];
    int p = beg;
    for (; p + 1 < end; p += 2) {
        int s0 = g_srclist[p], s1 = g_srclist[p + 1];
        float4 v0 = f4[s0 * 32 + lane];
        float4 v1 = f4[s1 * 32 + lane];
        acc.x += v0.x; acc.y += v0.y; acc.z += v0.z; acc.w += v0.w;
        acc.x += v1.x; acc.y += v1.y; acc.z += v1.z; acc.w += v1.w;
    }
    if (p < end) {
        int s = g_srclist[p];
        float4 v = f4[s * 32 + lane];
        acc.x += v.x; acc.y += v.y; acc.z += v.z; acc.w += v.w;
    }
    float di = g_dis[gw];
    float4 r;
    if (RELU) {
        float4 b = ((const float4*)bias)[lane];
        r.x = di * fmaxf(fmaf(di, acc.x, b.x), 0.f);
        r.y = di * fmaxf(fmaf(di, acc.y, b.y), 0.f);
        r.z = di * fmaxf(fmaf(di, acc.z, b.z), 0.f);
        r.w = di * fmaxf(fmaf(di, acc.w, b.w), 0.f);
    } else {
        r.x = di * acc.x; r.y = di * acc.y; r.z = di * acc.z; r.w = di * acc.w;
    }
    ((float4*)out)[gw * 32 + lane] = r;
}

__global__ __launch_bounds__(256) void agg1_kernel(const float* __restrict__ b1) {
    agg_body<true>(g_hw1, g_hs, b1);
}
__global__ __launch_bounds__(256) void agg2_kernel() {
    agg_body<false>(g_hs, g_g, nullptr);
}

// ------------------------- GEMM2 (fp32, known-good) -------------------------
__global__ __launch_bounds__(256, 2)
void gemm2_kernel(const float* __restrict__ Wmu, const float* __restrict__ bmu,
                  const float* __restrict__ Wlv, const float* __restrict__ blv,
                  float* __restrict__ out) {
    extern __shared__ float sm[];
    float* Wsm = sm;
    float* bsm = sm + HID * WS;
    float* xsm = bsm + HID;
    int tid = threadIdx.x, lane = tid & 31, warp = tid >> 5;

    for (int o = warp; o < HID; o += 8) {
#pragma unroll
        for (int m = 0; m < HID / 32; m++) {
            int k = m * 32 + lane;
            float w = (o < OUT_DIM) ? Wmu[o * HID + k] : Wlv[(o - OUT_DIM) * HID + k];
            Wsm[k * WS + o] = w;
        }
    }
    if (tid < HID) bsm[tid] = (tid < OUT_DIM) ? bmu[tid] : blv[tid - OUT_DIM];
    __syncthreads();

    const int RB = 64;
    int nblk = (NN + RB - 1) / RB;
    for (int blk = blockIdx.x; blk < nblk; blk += gridDim.x) {
        int row0 = blk * RB;
        __syncthreads();
#pragma unroll
        for (int i = 0; i < 8; i++) {
            int lin = tid + 256 * i;
            int r = lin >> 5, c4 = lin & 31;
            int row = row0 + r;
            float4 v = make_float4(0.f, 0.f, 0.f, 0.f);
            if (row < NN) v = ((const float4*)g_g)[row * (HID / 4) + c4];
            ((float4*)xsm)[r * (HID / 4) + c4] = v;
        }
        __syncthreads();

        ull acc[8][2];
#pragma unroll
        for (int r = 0; r < 8; r++) { acc[r][0] = 0ULL; acc[r][1] = 0ULL; }
        const float* xw = xsm + (warp * 8) * HID;

#pragma unroll 4
        for (int k = 0; k < HID; k++) {
            const float* wk = Wsm + k * WS;
            ull wp0 = pk2(wk[lane], wk[lane + 32]);
            ull wp1 = pk2(wk[lane + 64], wk[lane + 96]);
#pragma unroll
            for (int r = 0; r < 8; r++) {
                float xv = xw[r * HID + k];
                ull xp = pk2(xv, xv);
                acc[r][0] = fma2(xp, wp0, acc[r][0]);
                acc[r][1] = fma2(xp, wp1, acc[r][1]);
            }
        }
#pragma unroll
        for (int r = 0; r < 8; r++) {
            int row = row0 + warp * 8 + r;
            if (row < NN) {
                float2 a01 = upk2(acc[r][0]);
                float2 a23 = upk2(acc[r][1]);
                out[row * OUT_DIM + lane]             = a01.x + bsm[lane];
                out[row * OUT_DIM + lane + 32]        = a01.y + bsm[lane + 32];
                out[NOFF + row * OUT_DIM + lane]      = a23.x + bsm[lane + 64];
                out[NOFF + row * OUT_DIM + lane + 32] = a23.y + bsm[lane + 96];
            }
        }
    }
}

// ------------------------- launch -------------------------
extern "C" void kernel_launch(void* const* d_in, const int* in_sizes, int n_in,
                              void* d_out, int out_size) {
    const float* x   = (const float*)d_in[0];
    const void*  ei  = d_in[1];
    const float* W1  = (const float*)d_in[2];
    const float* b1  = (const float*)d_in[3];
    const float* Wmu = (const float*)d_in[4];
    const float* bmu = (const float*)d_in[5];
    const float* Wlv = (const float*)d_in[6];
    const float* blv = (const float*)d_in[7];
    float* out = (float*)d_out;

    void* p_count;  cudaGetSymbolAddress(&p_count, g_count);
    void* p_cursor; cudaGetSymbolAddress(&p_cursor, g_cursor);

    const int SMEM2 = (HID * WS + HID + 64 * HID) * (int)sizeof(float);
    cudaFuncSetAttribute(gemm1_mma_kernel, cudaFuncAttributeMaxDynamicSharedMemorySize, G1_SMEM);
    cudaFuncSetAttribute(gemm2_kernel, cudaFuncAttributeMaxDynamicSharedMemorySize, SMEM2);

    cudaMemsetAsync(p_count, 0, NN * sizeof(int));
    cudaMemsetAsync(p_cursor, 0, NN * sizeof(int));

    detect_kernel<<<1, 32>>>(ei);                                // #1
    convert_hist_kernel<<<(EE + 255) / 256, 256>>>(ei);          // #2
    dis_kernel<<<(NN + 255) / 256, 256>>>();                     // #3

    gemm1_mma_kernel<<<148, 256, G1_SMEM>>>(x, W1);              // #4  <- profiled

    scan_kernel<<<1, 1024>>>();                                  // #5
    scatter_kernel<<<(EE + 255) / 256, 256>>>();                 // #6

    int agg_blocks = (NN * 32 + 255) / 256;
    agg1_kernel<<<agg_blocks, 256>>>(b1);                        // #7
    agg2_kernel<<<agg_blocks, 256>>>();                          // #8

    gemm2_kernel<<<296, 256, SMEM2>>>(Wmu, bmu, Wlv, blv, out);  // #9
}

// round 9
// speedup vs baseline: 1.3721x; 1.1200x over previous
#include <cuda_runtime.h>
#include <cuda_bf16.h>
#include <cstdint>

#define NN 50000
#define EE 800000
#define IN_DIM 256
#define HID 128
#define OUT_DIM 64
#define NOFF (NN * OUT_DIM)

// ------------------------- device scratch -------------------------
__device__ int   g_count[NN];
__device__ int   g_cursor[NN];
__device__ int   g_offsets[NN + 1];
__device__ int   g_srclist[EE];
__device__ int   g_src[EE];
__device__ int   g_dst[EE];
__device__ float g_dis[NN];
__device__ float g_hw1[NN * HID];
__device__ float g_hs[NN * HID];
__device__ float g_g[NN * HID];
__device__ int   g_is64;

typedef unsigned long long ull;

// ------------------------- mma helpers -------------------------
__device__ __forceinline__ uint32_t smem_u32(const void* p) {
    uint32_t a;
    asm("{ .reg .u64 t; cvta.to.shared.u64 t, %1; cvt.u32.u64 %0, t; }" : "=r"(a) : "l"(p));
    return a;
}
__device__ __forceinline__ void ldsm_x4(uint32_t addr, uint32_t& r0, uint32_t& r1,
                                        uint32_t& r2, uint32_t& r3) {
    asm volatile("ldmatrix.sync.aligned.m8n8.x4.shared.b16 {%0,%1,%2,%3}, [%4];"
                 : "=r"(r0), "=r"(r1), "=r"(r2), "=r"(r3) : "r"(addr));
}
__device__ __forceinline__ void mma_bf16(float* d, uint32_t a0, uint32_t a1, uint32_t a2,
                                         uint32_t a3, uint32_t b0, uint32_t b1) {
    asm volatile(
        "mma.sync.aligned.m16n8k16.row.col.f32.bf16.bf16.f32 "
        "{%0,%1,%2,%3}, {%4,%5,%6,%7}, {%8,%9}, {%0,%1,%2,%3};"
        : "+f"(d[0]), "+f"(d[1]), "+f"(d[2]), "+f"(d[3])
        : "r"(a0), "r"(a1), "r"(a2), "r"(a3), "r"(b0), "r"(b1));
}
__device__ __forceinline__ uint32_t pack_bf16(float a, float b) {
    __nv_bfloat162 p = __floats2bfloat162_rn(a, b);
    return *reinterpret_cast<uint32_t*>(&p);
}
__device__ __forceinline__ float bf16_hi(float v) {
    return __bfloat162float(__float2bfloat16(v));
}

// ------------------------- small setup kernels -------------------------
__global__ void detect_kernel(const void* ei) {
    int lane = threadIdx.x;
    const long long* p = (const long long*)ei;
    int ok = 1;
    for (int i = lane; i < 1024; i += 32) {
        long long v = p[i];
        if (v < 0 || v >= NN) ok = 0;
    }
    unsigned m = __ballot_sync(0xffffffffu, ok);
    if (lane == 0) g_is64 = (m == 0xffffffffu) ? 1 : 0;
}

__global__ void convert_hist_kernel(const void* ei) {
    int i = blockIdx.x * blockDim.x + threadIdx.x;
    if (i >= EE) return;
    int s, d;
    if (g_is64) {
        const long long* p = (const long long*)ei;
        s = (int)p[i]; d = (int)p[EE + i];
    } else {
        const int* p = (const int*)ei;
        s = p[i]; d = p[EE + i];
    }
    s = min(max(s, 0), NN - 1);
    d = min(max(d, 0), NN - 1);
    g_src[i] = s; g_dst[i] = d;
    atomicAdd(&g_count[d], 1);
}

__global__ void dis_kernel() {
    int i = blockIdx.x * blockDim.x + threadIdx.x;
    if (i < NN) g_dis[i] = rsqrtf((float)(g_count[i] + 1));
}

__global__ __launch_bounds__(1024) void scan_kernel() {
    const int T = 1024, PER = (NN + T - 1) / T;
    int tid = threadIdx.x;
    int base = tid * PER;
    int run = 0;
    for (int i = 0; i < PER; i++) { int idx = base + i; if (idx < NN) run += g_count[idx]; }
    __shared__ int wsum[32];
    int lane = tid & 31, wid = tid >> 5;
    int inc = run;
    for (int d = 1; d < 32; d <<= 1) {
        int t = __shfl_up_sync(0xffffffffu, inc, d);
        if (lane >= d) inc += t;
    }
    if (lane == 31) wsum[wid] = inc;
    __syncthreads();
    if (wid == 0) {
        int w = wsum[lane];
        for (int d = 1; d < 32; d <<= 1) {
            int t = __shfl_up_sync(0xffffffffu, w, d);
            if (lane >= d) w += t;
        }
        wsum[lane] = w;
    }
    __syncthreads();
    int warpbase = (wid == 0) ? 0 : wsum[wid - 1];
    int acc = warpbase + inc - run;
    for (int i = 0; i < PER; i++) {
        int idx = base + i;
        if (idx <= NN) {
            g_offsets[idx] = acc;
            if (idx < NN) acc += g_count[idx];
        }
    }
}

__global__ void scatter_kernel() {
    int i = blockIdx.x * blockDim.x + threadIdx.x;
    if (i >= EE) return;
    int d = g_dst[i];
    int pos = g_offsets[d] + atomicAdd(&g_cursor[d], 1);
    g_srclist[pos] = g_src[i];
}

// ------------------------- GEMM1 via mma.sync bf16 hi/lo (proven R8) -----------------
#define SROW 528
#define OFF_WHI 0
#define OFF_WLO 67584
#define OFF_XHI 135168
#define OFF_XLO 168960
#define G1_SMEM 202752

__global__ __launch_bounds__(256, 1)
void gemm1_mma_kernel(const float* __restrict__ x, const float* __restrict__ W1) {
    extern __shared__ char smc[];
    uint32_t su = smem_u32(smc);
    int tid = threadIdx.x, lane = tid & 31, warp = tid >> 5;
    int wr = warp & 3;
    int wc = warp >> 2;

#pragma unroll
    for (int it = 0; it < 32; it++) {
        int idx = it * 256 + tid;
        int o = idx >> 6, kq = idx & 63;
        float4 v = ((const float4*)W1)[o * 64 + kq];
        float hx = bf16_hi(v.x), hy = bf16_hi(v.y), hz = bf16_hi(v.z), hw = bf16_hi(v.w);
        uint2 hp = make_uint2(pack_bf16(hx, hy), pack_bf16(hz, hw));
        uint2 lp = make_uint2(pack_bf16(v.x - hx, v.y - hy), pack_bf16(v.z - hz, v.w - hw));
        *reinterpret_cast<uint2*>(smc + OFF_WHI + o * SROW + kq * 8) = hp;
        *reinterpret_cast<uint2*>(smc + OFF_WLO + o * SROW + kq * 8) = lp;
    }

    uint32_t a_off = (uint32_t)((wr * 16 + (lane & 15)) * SROW + ((lane >> 4) << 4));
    uint32_t b_row = (uint32_t)((lane & 7) + ((lane >> 4) << 3));
    uint32_t b_off = (uint32_t)((wc * 64 + b_row) * SROW + (((lane >> 3) & 1) << 4));

    const int NT = (NN + 63) / 64;
    for (int t = blockIdx.x; t < NT; t += gridDim.x) {
        int row0 = t * 64;
        __syncthreads();
#pragma unroll
        for (int it = 0; it < 16; it++) {
            int idx = it * 256 + tid;
            int r = idx >> 6, kq = idx & 63;
            int grow = row0 + r;
            float4 v = make_float4(0.f, 0.f, 0.f, 0.f);
            if (grow < NN) v = ((const float4*)x)[grow * 64 + kq];
            float hx = bf16_hi(v.x), hy = bf16_hi(v.y), hz = bf16_hi(v.z), hw = bf16_hi(v.w);
            uint2 hp = make_uint2(pack_bf16(hx, hy), pack_bf16(hz, hw));
            uint2 lp = make_uint2(pack_bf16(v.x - hx, v.y - hy), pack_bf16(v.z - hz, v.w - hw));
            *reinterpret_cast<uint2*>(smc + OFF_XHI + r * SROW + kq * 8) = hp;
            *reinterpret_cast<uint2*>(smc + OFF_XLO + r * SROW + kq * 8) = lp;
        }
        __syncthreads();

        float acc[8][4];
#pragma unroll
        for (int j = 0; j < 8; j++)
#pragma unroll
            for (int q = 0; q < 4; q++) acc[j][q] = 0.f;

#pragma unroll 1
        for (int pass = 0; pass < 3; pass++) {
            uint32_t ab = su + ((pass == 1) ? OFF_XLO : OFF_XHI) + a_off;
            uint32_t bb = su + ((pass == 2) ? OFF_WLO : OFF_WHI) + b_off;
#pragma unroll
            for (int ks = 0; ks < 16; ks++) {
                uint32_t a0, a1, a2, a3;
                ldsm_x4(ab + ks * 32, a0, a1, a2, a3);
#pragma unroll
                for (int j = 0; j < 4; j++) {
                    uint32_t b0, b1, b2, b3;
                    ldsm_x4(bb + j * 16 * SROW + ks * 32, b0, b1, b2, b3);
                    mma_bf16(acc[2 * j],     a0, a1, a2, a3, b0, b1);
                    mma_bf16(acc[2 * j + 1], a0, a1, a2, a3, b2, b3);
                }
            }
        }

        int g = lane >> 2, tt = lane & 3;
        int r0g = row0 + wr * 16 + g;
        int r1g = r0g + 8;
        float di0 = (r0g < NN) ? g_dis[r0g] : 0.f;
        float di1 = (r1g < NN) ? g_dis[r1g] : 0.f;
#pragma unroll
        for (int j = 0; j < 8; j++) {
            int c = wc * 64 + j * 8 + 2 * tt;
            if (r0g < NN)
                *reinterpret_cast<float2*>(g_hw1 + r0g * HID + c) =
                    make_float2(di0 * acc[j][0], di0 * acc[j][1]);
            if (r1g < NN)
                *reinterpret_cast<float2*>(g_hw1 + r1g * HID + c) =
                    make_float2(di1 * acc[j][2], di1 * acc[j][3]);
        }
    }
}

// ------------------------- aggregation: warp per destination node -------------------
template <bool RELU>
__device__ __forceinline__ void agg_body(const float* __restrict__ feat,
                                         float* __restrict__ out,
                                         const float* __restrict__ bias) {
    int gw = (blockIdx.x * blockDim.x + threadIdx.x) >> 5;
    int lane = threadIdx.x & 31;
    if (gw >= NN) return;
    int beg = g_offsets[gw], end = g_offsets[gw + 1];
    const float4* f4 = (const float4*)feat;
    float4 acc = f4[gw * 32 + lane];
    int p = beg;
    for (; p + 1 < end; p += 2) {
        int s0 = g_srclist[p], s1 = g_srclist[p + 1];
        float4 v0 = f4[s0 * 32 + lane];
        float4 v1 = f4[s1 * 32 + lane];
        acc.x += v0.x; acc.y += v0.y; acc.z += v0.z; acc.w += v0.w;
        acc.x += v1.x; acc.y += v1.y; acc.z += v1.z; acc.w += v1.w;
    }
    if (p < end) {
        int s = g_srclist[p];
        float4 v = f4[s * 32 + lane];
        acc.x += v.x; acc.y += v.y; acc.z += v.z; acc.w += v.w;
    }
    float di = g_dis[gw];
    float4 r;
    if (RELU) {
        float4 b = ((const float4*)bias)[lane];
        r.x = di * fmaxf(fmaf(di, acc.x, b.x), 0.f);
        r.y = di * fmaxf(fmaf(di, acc.y, b.y), 0.f);
        r.z = di * fmaxf(fmaf(di, acc.z, b.z), 0.f);
        r.w = di * fmaxf(fmaf(di, acc.w, b.w), 0.f);
    } else {
        r.x = di * acc.x; r.y = di * acc.y; r.z = di * acc.z; r.w = di * acc.w;
    }
    ((float4*)out)[gw * 32 + lane] = r;
}

__global__ __launch_bounds__(256) void agg1_kernel(const float* __restrict__ b1) {
    agg_body<true>(g_hw1, g_hs, b1);
}
__global__ __launch_bounds__(256) void agg2_kernel() {
    agg_body<false>(g_hs, g_g, nullptr);
}

// ------------------------- GEMM2 via mma.sync bf16 hi/lo -----------------------------
// D[64rt][128o] = g_g @ [Wmu;Wlv]^T + [bmu;blv]; K=128 -> 8 k-steps x 3 passes.
// smem stride 272B (mod 128 = 16 -> LDSM conflict-free, same as gemm1's 528).
#define SROW2 272
#define OFF2_WHI 0
#define OFF2_WLO 34816
#define OFF2_XHI 69632
#define OFF2_XLO 87040
#define OFF2_BIAS 104448
#define G2_SMEM 104960

__global__ __launch_bounds__(256, 2)
void gemm2_mma_kernel(const float* __restrict__ Wmu, const float* __restrict__ bmu,
                      const float* __restrict__ Wlv, const float* __restrict__ blv,
                      float* __restrict__ out) {
    extern __shared__ char smc[];
    uint32_t su = smem_u32(smc);
    int tid = threadIdx.x, lane = tid & 31, warp = tid >> 5;
    int wr = warp & 3;
    int wc = warp >> 2;

    // stage W = concat(Wmu,Wlv) hi/lo once per block: 128 o x 32 float4
#pragma unroll
    for (int it = 0; it < 16; it++) {
        int idx = it * 256 + tid;
        int o = idx >> 5, kq = idx & 31;
        float4 v = (o < OUT_DIM) ? ((const float4*)Wmu)[o * 32 + kq]
                                 : ((const float4*)Wlv)[(o - OUT_DIM) * 32 + kq];
        float hx = bf16_hi(v.x), hy = bf16_hi(v.y), hz = bf16_hi(v.z), hw = bf16_hi(v.w);
        uint2 hp = make_uint2(pack_bf16(hx, hy), pack_bf16(hz, hw));
        uint2 lp = make_uint2(pack_bf16(v.x - hx, v.y - hy), pack_bf16(v.z - hz, v.w - hw));
        *reinterpret_cast<uint2*>(smc + OFF2_WHI + o * SROW2 + kq * 8) = hp;
        *reinterpret_cast<uint2*>(smc + OFF2_WLO + o * SROW2 + kq * 8) = lp;
    }
    if (tid < HID) {
        float b = (tid < OUT_DIM) ? bmu[tid] : blv[tid - OUT_DIM];
        *reinterpret_cast<float*>(smc + OFF2_BIAS + tid * 4) = b;
    }

    uint32_t a_off = (uint32_t)((wr * 16 + (lane & 15)) * SROW2 + ((lane >> 4) << 4));
    uint32_t b_row = (uint32_t)((lane & 7) + ((lane >> 4) << 3));
    uint32_t b_off = (uint32_t)((wc * 64 + b_row) * SROW2 + (((lane >> 3) & 1) << 4));

    const int NT = (NN + 63) / 64;
    for (int t = blockIdx.x; t < NT; t += gridDim.x) {
        int row0 = t * 64;
        __syncthreads();
#pragma unroll
        for (int it = 0; it < 8; it++) {
            int idx = it * 256 + tid;
            int r = idx >> 5, kq = idx & 31;
            int grow = row0 + r;
            float4 v = make_float4(0.f, 0.f, 0.f, 0.f);
            if (grow < NN) v = ((const float4*)g_g)[grow * 32 + kq];
            float hx = bf16_hi(v.x), hy = bf16_hi(v.y), hz = bf16_hi(v.z), hw = bf16_hi(v.w);
            uint2 hp = make_uint2(pack_bf16(hx, hy), pack_bf16(hz, hw));
            uint2 lp = make_uint2(pack_bf16(v.x - hx, v.y - hy), pack_bf16(v.z - hz, v.w - hw));
            *reinterpret_cast<uint2*>(smc + OFF2_XHI + r * SROW2 + kq * 8) = hp;
            *reinterpret_cast<uint2*>(smc + OFF2_XLO + r * SROW2 + kq * 8) = lp;
        }
        __syncthreads();

        float acc[8][4];
#pragma unroll
        for (int j = 0; j < 8; j++)
#pragma unroll
            for (int q = 0; q < 4; q++) acc[j][q] = 0.f;

#pragma unroll 1
        for (int pass = 0; pass < 3; pass++) {
            uint32_t ab = su + ((pass == 1) ? OFF2_XLO : OFF2_XHI) + a_off;
            uint32_t bb = su + ((pass == 2) ? OFF2_WLO : OFF2_WHI) + b_off;
#pragma unroll
            for (int ks = 0; ks < 8; ks++) {
                uint32_t a0, a1, a2, a3;
                ldsm_x4(ab + ks * 32, a0, a1, a2, a3);
#pragma unroll
                for (int j = 0; j < 4; j++) {
                    uint32_t b0, b1, b2, b3;
                    ldsm_x4(bb + j * 16 * SROW2 + ks * 32, b0, b1, b2, b3);
                    mma_bf16(acc[2 * j],     a0, a1, a2, a3, b0, b1);
                    mma_bf16(acc[2 * j + 1], a0, a1, a2, a3, b2, b3);
                }
            }
        }

        int g = lane >> 2, tt = lane & 3;
        int r0g = row0 + wr * 16 + g;
        int r1g = r0g + 8;
        float* obase = (wc == 0) ? out : (out + NOFF);
#pragma unroll
        for (int j = 0; j < 8; j++) {
            int cl = j * 8 + 2 * tt;            // local col 0..63 within mu or lv
            float2 bv = *reinterpret_cast<float2*>(smc + OFF2_BIAS + (wc * 64 + cl) * 4);
            if (r0g < NN)
                *reinterpret_cast<float2*>(obase + r0g * OUT_DIM + cl) =
                    make_float2(acc[j][0] + bv.x, acc[j][1] + bv.y);
            if (r1g < NN)
                *reinterpret_cast<float2*>(obase + r1g * OUT_DIM + cl) =
                    make_float2(acc[j][2] + bv.x, acc[j][3] + bv.y);
        }
    }
}

// ------------------------- launch -------------------------
extern "C" void kernel_launch(void* const* d_in, const int* in_sizes, int n_in,
                              void* d_out, int out_size) {
    const float* x   = (const float*)d_in[0];
    const void*  ei  = d_in[1];
    const float* W1  = (const float*)d_in[2];
    const float* b1  = (const float*)d_in[3];
    const float* Wmu = (const float*)d_in[4];
    const float* bmu = (const float*)d_in[5];
    const float* Wlv = (const float*)d_in[6];
    const float* blv = (const float*)d_in[7];
    float* out = (float*)d_out;

    void* p_count;  cudaGetSymbolAddress(&p_count, g_count);
    void* p_cursor; cudaGetSymbolAddress(&p_cursor, g_cursor);

    cudaFuncSetAttribute(gemm1_mma_kernel, cudaFuncAttributeMaxDynamicSharedMemorySize, G1_SMEM);
    cudaFuncSetAttribute(gemm2_mma_kernel, cudaFuncAttributeMaxDynamicSharedMemorySize, G2_SMEM);

    cudaMemsetAsync(p_count, 0, NN * sizeof(int));
    cudaMemsetAsync(p_cursor, 0, NN * sizeof(int));

    detect_kernel<<<1, 32>>>(ei);                                // #1
    convert_hist_kernel<<<(EE + 255) / 256, 256>>>(ei);          // #2
    dis_kernel<<<(NN + 255) / 256, 256>>>();                     // #3

    gemm1_mma_kernel<<<148, 256, G1_SMEM>>>(x, W1);              // #4  <- profiled

    scan_kernel<<<1, 1024>>>();                                  // #5
    scatter_kernel<<<(EE + 255) / 256, 256>>>();                 // #6

    int agg_blocks = (NN * 32 + 255) / 256;
    agg1_kernel<<<agg_blocks, 256>>>(b1);                        // #7
    agg2_kernel<<<agg_blocks, 256>>>();                          // #8

    gemm2_mma_kernel<<<296, 256, G2_SMEM>>>(Wmu, bmu, Wlv, blv, out);  // #9
}